// round 16
// baseline (speedup 1.0000x reference)
#include <cuda_runtime.h>
#include <cuda_fp16.h>

// InterpolateSparse2d on GB300 — round 14: double-buffered L2 ring,
// overlap by INDEPENDENT merged launches (zero intra-kernel sync).
// Pipeline (PB=4): T0 | {G0||T1} | {G1||T2} | {G2||T3} | G3.
// In a merged launch, gather reads the buffer filled by the PREVIOUS launch
// while transpose writes the other buffer — disjoint addresses, so no
// atomics/fences/spins; ordering rides on same-stream launch boundaries.
// R13 failed only on the merged-grid rank map (t = bid-1-bid/5 executed
// chunk -1 and shifted all chunks). Fixed: t = bid - bid/5.

#define BB 16
#define CC 64
#define HX 240
#define WX 320
#define NN 20000
#define HW (HX * WX)

#define PB 4                          // batches per phase
#define TCH (PB * (HW / 32))          // 9600 transpose chunks per phase
#define GCH (PB * NN / 32)            // 2500 gather chunks (32 pts each)
#define MGRID 12500                   // merged grid: bid%5==4 -> gather

// Two ring buffers: 2 * 4 batches * 76800 px * 128B = 78.6 MB (< L2).
__device__ uint4 g_ring[2L * PB * HW * 8];

// ---------------------------------------------------------------------------
__device__ __forceinline__ void transpose_chunk(const float* __restrict__ x,
                                                int k0, int buf, int chunk,
                                                int tid, float* tile)
{
    int lb = chunk / (HW / 32);
    int b  = k0 + lb;
    int p0 = (chunk % (HW / 32)) * 32;

    int pl = tid & 31;            // pixel lane 0..31
    int c0 = tid >> 5;            // 0..7

    const float* src = x + (long long)b * CC * HW + p0;
    float v[8];
    #pragma unroll
    for (int i = 0; i < 8; i++) {
        int c = c0 + i * 8;
        // evict-first: x is single-use; protect the ring's L2 residency.
        v[i] = __ldcs(src + (long long)c * HW + pl);
    }
    #pragma unroll
    for (int i = 0; i < 8; i++)
        tile[(c0 + i * 8) * 33 + pl] = v[i];
    __syncthreads();

    int c2 = tid & 31;            // half2 index: channels 2*c2, 2*c2+1
    int pg = tid >> 5;            // 0..7
    __half2* dst = (__half2*)(g_ring +
                   ((long long)buf * PB * HW + (long long)lb * HW + p0) * 8);
    #pragma unroll
    for (int i = 0; i < 4; i++) {
        int p = pg + i * 8;
        float lo = tile[(2 * c2)     * 33 + p];
        float hi = tile[(2 * c2 + 1) * 33 + p];
        dst[p * 32 + c2] = __floats2half2_rn(lo, hi);
    }
    __syncthreads();              // tile safe for caller reuse
}

__device__ __forceinline__ void gather_chunk(const float* __restrict__ pos,
                                             float Wf, float Hf,
                                             int k0, int buf, int chunk,
                                             int tid, float* __restrict__ out)
{
    int lane8 = tid & 7;          // 8 channels per lane
    int pl    = chunk * 32 + (tid >> 3);      // local point in phase
    int lb    = pl / NN;                      // ring slot within buffer
    long long pn = (long long)(k0 + lb) * NN + (pl - lb * NN);

    float posx = pos[pn * 2 + 0];
    float posy = pos[pn * 2 + 1];

    // Match reference arithmetic order: pos * (Wx-1) / W
    float px = posx * (float)(WX - 1) / Wf;
    float py = posy * (float)(HX - 1) / Hf;

    int x0 = (int)floorf(px);
    int y0 = (int)floorf(py);
    x0 = min(max(x0, 0), WX - 1);
    y0 = min(max(y0, 0), HX - 1);
    int x1 = min(x0 + 1, WX - 1);
    int y1 = min(y0 + 1, HX - 1);

    float x0f = (float)x0, x1f = (float)x1;
    float y0f = (float)y0, y1f = (float)y1;

    float wa = (x1f - px) * (y1f - py);
    float wb = (x1f - px) * (py - y0f);
    float wc = (px - x0f) * (y1f - py);
    float wd = (px - x0f) * (py - y0f);

    const uint4* base = g_ring + (long long)buf * PB * HW * 8;
    long long rowb = (long long)lb * HX;
    long long i00 = ((rowb + y0) * WX + x0) * 8 + lane8;
    long long i01 = ((rowb + y0) * WX + x1) * 8 + lane8;
    long long i10 = ((rowb + y1) * WX + x0) * 8 + lane8;
    long long i11 = ((rowb + y1) * WX + x1) * 8 + lane8;

    uint4 A  = __ldg(base + i00);
    uint4 Bv = __ldg(base + i10);
    uint4 Cv = __ldg(base + i01);
    uint4 D  = __ldg(base + i11);

    float r[8];
    const unsigned* au = (const unsigned*)&A;
    const unsigned* bu = (const unsigned*)&Bv;
    const unsigned* cu = (const unsigned*)&Cv;
    const unsigned* du = (const unsigned*)&D;
    #pragma unroll
    for (int j = 0; j < 4; j++) {
        float2 fa = __half22float2(*(const __half2*)&au[j]);
        float2 fb = __half22float2(*(const __half2*)&bu[j]);
        float2 fc = __half22float2(*(const __half2*)&cu[j]);
        float2 fd = __half22float2(*(const __half2*)&du[j]);
        r[2 * j + 0] = wa * fa.x + wb * fb.x + wc * fc.x + wd * fd.x;
        r[2 * j + 1] = wa * fa.y + wb * fb.y + wc * fc.y + wd * fd.y;
    }

    float4* o = (float4*)out;
    long long ob = pn * 16 + lane8 * 2;
    __stcs(o + ob + 0, make_float4(r[0], r[1], r[2], r[3]));
    __stcs(o + ob + 1, make_float4(r[4], r[5], r[6], r[7]));
}

// ---------------------------------------------------------------------------
__global__ void __launch_bounds__(256)
k_transpose(const float* __restrict__ x, int k0, int buf)
{
    __shared__ float tile[64 * 33];
    transpose_chunk(x, k0, buf, blockIdx.x, threadIdx.x, tile);
}

__global__ void __launch_bounds__(256)
k_gather(const float* __restrict__ pos,
         const int* __restrict__ Hp, const int* __restrict__ Wp,
         float* __restrict__ out, int k0, int buf)
{
    gather_chunk(pos, (float)(*Wp), (float)(*Hp), k0, buf,
                 blockIdx.x, threadIdx.x, out);
}

// Merged, fully independent halves: gather(gk0 from gbuf) + transpose(tk0 to
// tbuf), gbuf != tbuf. 1-in-5 blocks are gather so both run throughout.
__global__ void __launch_bounds__(256)
k_merged(const float* __restrict__ x, const float* __restrict__ pos,
         const int* __restrict__ Hp, const int* __restrict__ Wp,
         float* __restrict__ out,
         int tk0, int tbuf, int gk0, int gbuf)
{
    __shared__ float tile[64 * 33];
    int bid = blockIdx.x;
    if ((bid % 5) == 4) {
        int g = bid / 5;                        // 0..2499
        gather_chunk(pos, (float)(*Wp), (float)(*Hp), gk0, gbuf,
                     g, threadIdx.x, out);
    } else {
        // Non-gather rank: gather bids strictly below bid = bid/5.
        int t = bid - bid / 5;                  // 0..9999
        if (t < TCH)
            transpose_chunk(x, tk0, tbuf, t, threadIdx.x, tile);
    }
}

extern "C" void kernel_launch(void* const* d_in, const int* in_sizes, int n_in,
                              void* d_out, int out_size)
{
    const float* x   = (const float*)d_in[0];
    const float* pos = (const float*)d_in[1];
    const int*   Hp  = (const int*)d_in[2];
    const int*   Wp  = (const int*)d_in[3];
    float* out = (float*)d_out;

    // T0 -> {G0||T1} -> {G1||T2} -> {G2||T3} -> G3, buffers alternate.
    k_transpose<<<TCH, 256>>>(x, 0, 0);
    k_merged<<<MGRID, 256>>>(x, pos, Hp, Wp, out, /*T*/ 4,  1, /*G*/ 0,  0);
    k_merged<<<MGRID, 256>>>(x, pos, Hp, Wp, out, /*T*/ 8,  0, /*G*/ 4,  1);
    k_merged<<<MGRID, 256>>>(x, pos, Hp, Wp, out, /*T*/ 12, 1, /*G*/ 8,  0);
    k_gather<<<GCH, 256>>>(pos, Hp, Wp, out, 12, 1);
}

// round 17
// speedup vs baseline: 1.0342x; 1.0342x over previous
#include <cuda_runtime.h>
#include <cuda_fp16.h>

// InterpolateSparse2d on GB300 — round 15: R11 ring + MLP-8 gather.
// Overlap is conclusively dead (3 designs, all ~4TB/s mixed vs ~7TB/s
// homogeneous). R11 (PB=4 ring, 8 serial launches) is the best mechanism:
// transpose phases at full rate, gather scratch reads 100% L2 hits. Its only
// fat: gather phases are L2-LATENCY bound (10.85us vs 5.5us bandwidth floor,
// MLP=4). This round: 2 points per thread -> 8 independent 16B corner loads
// in flight (MLP=8), 1250 blocks/phase.

#define BB 16
#define CC 64
#define HX 240
#define WX 320
#define NN 20000
#define HW (HX * WX)

#define PB 4                         // batches per super-phase
#define PPTS (PB * NN)               // 80000 points per phase
#define HALF (PPTS / 2)              // 40000

// Ring: 4 batches * 76800 px * 128B = 39.3 MB (reused each phase, L2-hot).
__device__ uint4 g_ring[(long long)PB * HW * 8];

// ---------------------------------------------------------------------------
// Transpose phase: [b, C,H,W] fp32 -> ring slot [lb, H,W,C] fp16, b = k0+lb.
// ---------------------------------------------------------------------------
__global__ void __launch_bounds__(256)
transpose_phase(const float* __restrict__ x, int k0)
{
    __shared__ float tile[64 * 33];   // [c][pixel], stride 33: conflict-free

    int blk = blockIdx.x;                  // lb * (HW/32) + pixel_chunk
    int lb  = blk / (HW / 32);
    int b   = k0 + lb;
    int p0  = (blk % (HW / 32)) * 32;

    int t  = threadIdx.x;
    int pl = t & 31;          // pixel lane 0..31
    int c0 = t >> 5;          // 0..7

    const float* src = x + (long long)b * CC * HW + p0;
    #pragma unroll
    for (int i = 0; i < 8; i++) {
        int c = c0 + i * 8;
        // evict-first: x is single-use; protect the ring's L2 residency.
        tile[c * 33 + pl] = __ldcs(src + (long long)c * HW + pl);
    }
    __syncthreads();

    int c2 = t & 31;          // half2 index: channels 2*c2, 2*c2+1
    int pg = t >> 5;          // 0..7
    __half2* dst = (__half2*)(g_ring + ((long long)lb * HW + p0) * 8);
    #pragma unroll
    for (int i = 0; i < 4; i++) {
        int p = pg + i * 8;
        float lo = tile[(2 * c2)     * 33 + p];
        float hi = tile[(2 * c2 + 1) * 33 + p];
        dst[p * 32 + c2] = __floats2half2_rn(lo, hi);
    }
}

// ---------------------------------------------------------------------------
// Gather phase: 2 points per thread, 8 corner loads in flight (MLP=8).
// 8 threads per point-slot; each thread owns 8 channels of both points.
// ---------------------------------------------------------------------------
struct PtIdx {
    long long i00, i01, i10, i11, pn;
    float wa, wb, wc, wd;
};

__device__ __forceinline__ void point_setup(const float* __restrict__ pos,
                                            float Wf, float Hf,
                                            int k0, int pl, int lane8,
                                            PtIdx* P)
{
    int lb = pl / NN;              // ring slot
    long long pn = (long long)(k0 + lb) * NN + (pl - lb * NN);
    P->pn = pn;

    float px = pos[pn * 2 + 0] * (float)(WX - 1) / Wf;
    float py = pos[pn * 2 + 1] * (float)(HX - 1) / Hf;

    int x0 = min(max((int)floorf(px), 0), WX - 1);
    int y0 = min(max((int)floorf(py), 0), HX - 1);
    int x1 = min(x0 + 1, WX - 1);
    int y1 = min(y0 + 1, HX - 1);

    float x0f = (float)x0, x1f = (float)x1;
    float y0f = (float)y0, y1f = (float)y1;

    P->wa = (x1f - px) * (y1f - py);
    P->wb = (x1f - px) * (py - y0f);
    P->wc = (px - x0f) * (y1f - py);
    P->wd = (px - x0f) * (py - y0f);

    long long rowb = (long long)lb * HX;
    P->i00 = ((rowb + y0) * WX + x0) * 8 + lane8;
    P->i01 = ((rowb + y0) * WX + x1) * 8 + lane8;
    P->i10 = ((rowb + y1) * WX + x0) * 8 + lane8;
    P->i11 = ((rowb + y1) * WX + x1) * 8 + lane8;
}

__device__ __forceinline__ void point_finish(const uint4& A, const uint4& Bv,
                                             const uint4& Cv, const uint4& D,
                                             const PtIdx& P, int lane8,
                                             float* __restrict__ out)
{
    float r[8];
    const unsigned* au = (const unsigned*)&A;
    const unsigned* bu = (const unsigned*)&Bv;
    const unsigned* cu = (const unsigned*)&Cv;
    const unsigned* du = (const unsigned*)&D;
    #pragma unroll
    for (int j = 0; j < 4; j++) {
        float2 fa = __half22float2(*(const __half2*)&au[j]);
        float2 fb = __half22float2(*(const __half2*)&bu[j]);
        float2 fc = __half22float2(*(const __half2*)&cu[j]);
        float2 fd = __half22float2(*(const __half2*)&du[j]);
        r[2 * j + 0] = P.wa * fa.x + P.wb * fb.x + P.wc * fc.x + P.wd * fd.x;
        r[2 * j + 1] = P.wa * fa.y + P.wb * fb.y + P.wc * fc.y + P.wd * fd.y;
    }
    float4* o = (float4*)out;
    long long ob = P.pn * 16 + lane8 * 2;
    __stcs(o + ob + 0, make_float4(r[0], r[1], r[2], r[3]));
    __stcs(o + ob + 1, make_float4(r[4], r[5], r[6], r[7]));
}

__global__ void __launch_bounds__(256)
gather_phase(const float* __restrict__ pos,
             const int* __restrict__ Hp,
             const int* __restrict__ Wp,
             float* __restrict__ out, int k0)
{
    int t = blockIdx.x * blockDim.x + threadIdx.x;
    int lane8 = t & 7;             // 8 channels per lane
    int pl0 = t >> 3;              // first point slot (0..39999)
    if (pl0 >= HALF) return;
    int pl1 = pl0 + HALF;          // second point slot

    float Wf = (float)(*Wp);
    float Hf = (float)(*Hp);

    PtIdx Pa, Pb;
    point_setup(pos, Wf, Hf, k0, pl0, lane8, &Pa);
    point_setup(pos, Wf, Hf, k0, pl1, lane8, &Pb);

    // 8 independent 16B loads in flight before any use (MLP=8).
    uint4 A0 = __ldg(g_ring + Pa.i00);
    uint4 B0 = __ldg(g_ring + Pa.i10);
    uint4 C0 = __ldg(g_ring + Pa.i01);
    uint4 D0 = __ldg(g_ring + Pa.i11);
    uint4 A1 = __ldg(g_ring + Pb.i00);
    uint4 B1 = __ldg(g_ring + Pb.i10);
    uint4 C1 = __ldg(g_ring + Pb.i01);
    uint4 D1 = __ldg(g_ring + Pb.i11);

    point_finish(A0, B0, C0, D0, Pa, lane8, out);
    point_finish(A1, B1, C1, D1, Pb, lane8, out);
}

extern "C" void kernel_launch(void* const* d_in, const int* in_sizes, int n_in,
                              void* d_out, int out_size)
{
    const float* x   = (const float*)d_in[0];
    const float* pos = (const float*)d_in[1];
    const int*   Hp  = (const int*)d_in[2];
    const int*   Wp  = (const int*)d_in[3];
    float* out = (float*)d_out;

    const int tblocks = PB * (HW / 32);                    // 9600
    const int gblocks = (HALF * 8 + 255) / 256;            // 1250

    for (int k0 = 0; k0 < BB; k0 += PB) {
        transpose_phase<<<tblocks, 256>>>(x, k0);
        gather_phase<<<gblocks, 256>>>(pos, Hp, Wp, out, k0);
    }
}